// round 15
// baseline (speedup 1.0000x reference)
#include <cuda_runtime.h>
#include <cuda_fp16.h>
#include <math.h>
#include <stdint.h>

#define N_ELEC 64
#define N_NUC  16
#define N_PART 80
#define BASIS  32
#define KDIM   128
#define DDIM   128
#define BSZ    256
#define LAYERS 3
#define NBI    (BSZ * N_ELEC)

#define TILES_PER_CTA 8
#define CFC_GRID (NBI / TILES_PER_CTA)   // 2048

// cfconv SMEM word-layout (4-byte words): d x2, h, zs, red
#define DPADW 20
#define HPADW 68
#define ZPAD  132
#define OFF_D0 0
#define OFF_D1 (N_PART * DPADW)              // 1600
#define OFF_H  (2 * N_PART * DPADW)          // 3200
#define OFF_ZS (OFF_H + N_PART * HPADW)      // 8640
#define OFF_RED (OFF_ZS + N_PART * ZPAD)     // 19200
#define SMEM_WORDS (OFF_RED + 256)           // 19456 words = 77824 B

// side-kernel SMEM row stride (words)
#define ASTR 68

// Scratch (no cudaMalloc allowed)
__device__ float g_zs[BSZ * N_PART * KDIM];      // (b, j, k)
__device__ float g_zsout[BSZ * N_ELEC * KDIM];   // cfconv output
__device__ float g_zrow[2 * KDIM];               // layer-0 zs rows (up, dn)

__device__ __forceinline__ float ssp_f(float x) {
    float ax = fabsf(x);
    return fmaxf(x, 0.0f) + __logf(1.0f + __expf(-ax)) - 0.69314718055994530942f;
}

__device__ __forceinline__ uint32_t pack_h2(float lo, float hi) {
    __half2 h = __floats2half2_rn(lo, hi);
    return *(uint32_t*)&h;
}

__device__ __forceinline__ uint32_t smem_u32(const void* p) {
    uint32_t a;
    asm("{ .reg .u64 t; cvta.to.shared.u64 t, %1; cvt.u32.u64 %0, t; }" : "=r"(a) : "l"(p));
    return a;
}

// m16n8k16 fp16 mma, fp32 accumulate
__device__ __forceinline__ void mma_f16(float* d, const uint32_t* a,
                                        uint32_t b0, uint32_t b1) {
    asm volatile(
        "mma.sync.aligned.m16n8k16.row.col.f32.f16.f16.f32 "
        "{%0,%1,%2,%3}, {%4,%5,%6,%7}, {%8,%9}, {%0,%1,%2,%3};"
        : "+f"(d[0]), "+f"(d[1]), "+f"(d[2]), "+f"(d[3])
        : "r"(a[0]), "r"(a[1]), "r"(a[2]), "r"(a[3]), "r"(b0), "r"(b1));
}

// m16n8k16 fp16 mma, fp16 accumulate (2 packed c/d regs)
__device__ __forceinline__ void mma_f16h(uint32_t* c, const uint32_t* a,
                                         uint32_t b0, uint32_t b1) {
    asm volatile(
        "mma.sync.aligned.m16n8k16.row.col.f16.f16.f16.f16 "
        "{%0,%1}, {%2,%3,%4,%5}, {%6,%7}, {%0,%1};"
        : "+r"(c[0]), "+r"(c[1])
        : "r"(a[0]), "r"(a[1]), "r"(a[2]), "r"(a[3]), "r"(b0), "r"(b1));
}

// ldmatrix x4 (sm_75+ baseline PTX)
#define LDSM4(r0, r1, r2, r3, addr) \
    asm volatile("ldmatrix.sync.aligned.m8n8.x4.shared.b16 {%0,%1,%2,%3}, [%4];" \
                 : "=r"(r0), "=r"(r1), "=r"(r2), "=r"(r3) : "r"(addr))

// ---------------------------------------------------------------------------
__global__ void z0_kernel(const float* __restrict__ emb_e,
                          const float* __restrict__ eiW) {
    __shared__ float eup[DDIM], edn[DDIM];
    int k = threadIdx.x;
    eup[k] = emb_e[k];
    edn[k] = emb_e[N_ELEC / 2 * DDIM + k];
    __syncthreads();
    float au = 0.f, ad = 0.f;
#pragma unroll 4
    for (int d = 0; d < DDIM; ++d) {
        float w = eiW[d * KDIM + k];
        au = fmaf(eup[d], w, au);
        ad = fmaf(edn[d], w, ad);
    }
    g_zrow[k] = au;
    g_zrow[KDIM + k] = ad;
}

__global__ void fill0_kernel(const float* __restrict__ emb_e,
                             const float* __restrict__ emb_n,
                             float* __restrict__ xs) {
    int idx = blockIdx.x * blockDim.x + threadIdx.x;
    if (idx < BSZ * N_PART * KDIM) {
        int jk = idx % (N_PART * KDIM);
        int j = jk >> 7, k = jk & 127;
        float v;
        if (j < N_ELEC) v = g_zrow[(j >= N_ELEC / 2 ? KDIM : 0) + k];
        else            v = emb_n[(j - N_ELEC) * KDIM + k];
        g_zs[idx] = v;
    }
    if (idx < BSZ * N_ELEC * DDIM) {
        xs[idx] = emb_e[idx % (N_ELEC * DDIM)];
    }
}

// ---------------------------------------------------------------------------
// Fused output MLP + next-layer zs (unchanged from R13)
// ---------------------------------------------------------------------------
extern __shared__ uint32_t dyn_smem_w[];

__global__ void __launch_bounds__(256) outzs_mma_kernel(
    const float* __restrict__ eoW1, const float* __restrict__ eob1,
    const float* __restrict__ eoW2, const float* __restrict__ eob2,
    const float* __restrict__ eiW_next,
    float* __restrict__ xs)
{
    uint32_t* w1_w = dyn_smem_w;
    uint32_t* w2_w = dyn_smem_w + 128 * ASTR;
    uint32_t* a_w  = dyn_smem_w + 2 * 128 * ASTR;
    uint32_t* ei_w = dyn_smem_w + 3 * 128 * ASTR;
    float*    bias = (float*)(dyn_smem_w + 4 * 128 * ASTR);

    const int tid  = threadIdx.x;
    const int wid  = tid >> 5;
    const int lane = tid & 31;
    const int g    = lane >> 2;
    const int tg   = lane & 3;
    const int rblk = blockIdx.x * 128;
    const int r0   = wid * 16 + g;

    for (int idx = tid; idx < 128 * 64; idx += 256) {
        int kp = idx >> 7, d = idx & 127;
        w1_w[d * ASTR + kp] = pack_h2(eoW1[(2 * kp) * DDIM + d],
                                      eoW1[(2 * kp + 1) * DDIM + d]);
        w2_w[d * ASTR + kp] = pack_h2(eoW2[(2 * kp) * DDIM + d],
                                      eoW2[(2 * kp + 1) * DDIM + d]);
        if (eiW_next)
            ei_w[d * ASTR + kp] = pack_h2(eiW_next[(2 * kp) * KDIM + d],
                                          eiW_next[(2 * kp + 1) * KDIM + d]);
    }
    for (int idx = tid; idx < 128 * 64; idx += 256) {
        int r = idx >> 6, kw = idx & 63;
        float2 v = *(const float2*)&g_zsout[(size_t)(rblk + r) * KDIM + kw * 2];
        a_w[r * ASTR + kw] = pack_h2(v.x, v.y);
    }
    if (tid < 128) { bias[tid] = eob1[tid]; bias[128 + tid] = eob2[tid]; }
    __syncthreads();

    float acc[16][4];
#pragma unroll
    for (int nt = 0; nt < 16; ++nt) {
        acc[nt][0] = 0.f; acc[nt][1] = 0.f; acc[nt][2] = 0.f; acc[nt][3] = 0.f;
    }
#pragma unroll
    for (int kk = 0; kk < 8; ++kk) {
        uint32_t a[4];
        int ab = r0 * ASTR + kk * 8 + tg;
        a[0] = a_w[ab];
        a[1] = a_w[ab + 8 * ASTR];
        a[2] = a_w[ab + 4];
        a[3] = a_w[ab + 8 * ASTR + 4];
#pragma unroll
        for (int nt = 0; nt < 16; ++nt) {
            int nb = (nt * 8 + g) * ASTR + kk * 8 + tg;
            mma_f16(acc[nt], a, w1_w[nb], w1_w[nb + 4]);
        }
    }
    __syncthreads();

#pragma unroll
    for (int nt = 0; nt < 16; ++nt) {
        int d0 = nt * 8 + 2 * tg;
        float ba = bias[d0], bb = bias[d0 + 1];
        w1_w[r0 * ASTR + nt * 4 + tg] =
            pack_h2(ssp_f(acc[nt][0] + ba), ssp_f(acc[nt][1] + bb));
        w1_w[(r0 + 8) * ASTR + nt * 4 + tg] =
            pack_h2(ssp_f(acc[nt][2] + ba), ssp_f(acc[nt][3] + bb));
        acc[nt][0] = 0.f; acc[nt][1] = 0.f; acc[nt][2] = 0.f; acc[nt][3] = 0.f;
    }
    __syncthreads();

#pragma unroll
    for (int kk = 0; kk < 8; ++kk) {
        uint32_t a[4];
        int ab = r0 * ASTR + kk * 8 + tg;
        a[0] = w1_w[ab];
        a[1] = w1_w[ab + 8 * ASTR];
        a[2] = w1_w[ab + 4];
        a[3] = w1_w[ab + 8 * ASTR + 4];
#pragma unroll
        for (int nt = 0; nt < 16; ++nt) {
            int nb = (nt * 8 + g) * ASTR + kk * 8 + tg;
            mma_f16(acc[nt], a, w2_w[nb], w2_w[nb + 4]);
        }
    }

    float* x0 = xs + (size_t)(rblk + r0) * DDIM;
    float* x1 = xs + (size_t)(rblk + r0 + 8) * DDIM;
#pragma unroll
    for (int nt = 0; nt < 16; ++nt) {
        int d0 = nt * 8 + 2 * tg;
        float ba = bias[128 + d0], bb = bias[128 + d0 + 1];
        float2 v0 = *(float2*)&x0[d0];
        float2 v1 = *(float2*)&x1[d0];
        v0.x += acc[nt][0] + ba;  v0.y += acc[nt][1] + bb;
        v1.x += acc[nt][2] + ba;  v1.y += acc[nt][3] + bb;
        *(float2*)&x0[d0] = v0;
        *(float2*)&x1[d0] = v1;
        if (eiW_next) {
            a_w[r0 * ASTR + nt * 4 + tg]       = pack_h2(v0.x, v0.y);
            a_w[(r0 + 8) * ASTR + nt * 4 + tg] = pack_h2(v1.x, v1.y);
        }
    }

    if (!eiW_next) return;
    __syncthreads();

#pragma unroll
    for (int nt = 0; nt < 16; ++nt) {
        acc[nt][0] = 0.f; acc[nt][1] = 0.f; acc[nt][2] = 0.f; acc[nt][3] = 0.f;
    }
#pragma unroll
    for (int kk = 0; kk < 8; ++kk) {
        uint32_t a[4];
        int ab = r0 * ASTR + kk * 8 + tg;
        a[0] = a_w[ab];
        a[1] = a_w[ab + 8 * ASTR];
        a[2] = a_w[ab + 4];
        a[3] = a_w[ab + 8 * ASTR + 4];
#pragma unroll
        for (int nt = 0; nt < 16; ++nt) {
            int nb = (nt * 8 + g) * ASTR + kk * 8 + tg;
            mma_f16(acc[nt], a, ei_w[nb], ei_w[nb + 4]);
        }
    }
    const int row0 = rblk + r0;
    const int b0 = row0 >> 6, j0r = row0 & 63;
    const int row1 = row0 + 8;
    const int b1 = row1 >> 6, j1r = row1 & 63;
    float* z0p = g_zs + ((size_t)b0 * N_PART + j0r) * KDIM;
    float* z1p = g_zs + ((size_t)b1 * N_PART + j1r) * KDIM;
#pragma unroll
    for (int nt = 0; nt < 16; ++nt) {
        int k0 = nt * 8 + 2 * tg;
        *(float2*)&z0p[k0] = make_float2(acc[nt][0], acc[nt][1]);
        *(float2*)&z1p[k0] = make_float2(acc[nt][2], acc[nt][3]);
    }
}

// ---------------------------------------------------------------------------
// cfconv: warps = 4 m-groups (32 rows) x 2 j-groups (40 cols).
// Each B fragment feeds 2 mma -> SMEM crossbar traffic halved.
// fp16 accumulators fund the doubled A-fragment registers (2 CTAs/SM kept).
// ---------------------------------------------------------------------------
__global__ void __launch_bounds__(256, 2) cfconv_mma_kernel(
    const float* __restrict__ dists,
    const float* __restrict__ kW1, const float* __restrict__ kb1,
    const float* __restrict__ kW2, const float* __restrict__ kb2)
{
    uint32_t* d_sw0 = dyn_smem_w + OFF_D0;
    uint32_t* d_sw1 = dyn_smem_w + OFF_D1;
    __half*   h_sh  = (__half*)(dyn_smem_w + OFF_H);
    float*    zs_s  = (float*)(dyn_smem_w + OFF_ZS);
    float*    red   = (float*)(dyn_smem_w + OFF_RED);   // [2][128]

    const int tid  = threadIdx.x;
    const int wid  = tid >> 5;
    const int lane = tid & 31;
    const int g    = lane >> 2;
    const int tg   = lane & 3;
    const int mg   = wid >> 1;          // 0..3 -> rows mg*32 .. mg*32+31
    const int jg   = wid & 1;           // 0..1 -> cols jg*40 .. jg*40+39
    const int mbase = mg * 32;
    const int jbase = jg * 40;
    // 4 output rows per thread: mt0: r=mbase+g, +8 ; mt1: mbase+16+g, +8
    const int ra0 = mbase + g,      ra1 = ra0 + 8;
    const int rb0 = mbase + 16 + g, rb1 = rb0 + 8;

    const int role = lane >> 3;
    const int rrow = lane & 7;
    const uint32_t doff = (jbase + rrow) * (DPADW * 4) + (role >> 1) * 32 + (role & 1) * 16;
    const uint32_t hoff = (jbase + rrow) * (HPADW * 4) + (role >> 1) * 32 + (role & 1) * 16;
    const uint32_t ldsm_d0 = smem_u32(d_sw0) + doff;
    const uint32_t ldsm_d1 = smem_u32(d_sw1) + doff;
    const uint32_t ldsm_h  = smem_u32(h_sh) + hoff;

    // A fragments: GEMM1 [kstep][mtile][4], GEMM2 [kstep][mtile][4]
    uint32_t a1r[2][2][4];
#pragma unroll
    for (int kk = 0; kk < 2; ++kk) {
        int f = kk * 16 + 2 * tg;
#pragma unroll
        for (int mt = 0; mt < 2; ++mt) {
            int q0 = mbase + mt * 16 + g, q1 = q0 + 8;
            a1r[kk][mt][0] = pack_h2(kW1[f * KDIM + q0],       kW1[(f + 1) * KDIM + q0]);
            a1r[kk][mt][1] = pack_h2(kW1[f * KDIM + q1],       kW1[(f + 1) * KDIM + q1]);
            a1r[kk][mt][2] = pack_h2(kW1[(f + 8) * KDIM + q0], kW1[(f + 9) * KDIM + q0]);
            a1r[kk][mt][3] = pack_h2(kW1[(f + 8) * KDIM + q1], kW1[(f + 9) * KDIM + q1]);
        }
    }
    uint32_t a2r[8][2][4];
#pragma unroll
    for (int kk = 0; kk < 8; ++kk) {
        int mm = kk * 16 + 2 * tg;
#pragma unroll
        for (int mt = 0; mt < 2; ++mt) {
            int q0 = mbase + mt * 16 + g, q1 = q0 + 8;
            a2r[kk][mt][0] = pack_h2(kW2[mm * KDIM + q0],       kW2[(mm + 1) * KDIM + q0]);
            a2r[kk][mt][1] = pack_h2(kW2[mm * KDIM + q1],       kW2[(mm + 1) * KDIM + q1]);
            a2r[kk][mt][2] = pack_h2(kW2[(mm + 8) * KDIM + q0], kW2[(mm + 9) * KDIM + q0]);
            a2r[kk][mt][3] = pack_h2(kW2[(mm + 8) * KDIM + q1], kW2[(mm + 9) * KDIM + q1]);
        }
    }
    // per-row bias as broadcast half2
    const __half2 kb1h[4] = {
        __half2half2(__float2half_rn(kb1[ra0])), __half2half2(__float2half_rn(kb1[ra1])),
        __half2half2(__float2half_rn(kb1[rb0])), __half2half2(__float2half_rn(kb1[rb1])) };
    const float kb2v[4] = { kb2[ra0], kb2[ra1], kb2[rb0], kb2[rb1] };

    const __half2 D1 = __float2half2_rn( 0.5f);
    const __half2 D2 = __float2half2_rn(-8.3333333e-2f);
    const __half2 D3 = __float2half2_rn( 2.2222222e-2f);
    const __half2 D4 = __float2half2_rn(-6.7460317e-3f);
    const __half2 D5 = __float2half2_rn( 2.1869489e-3f);
    const __half2 HHALF = __float2half2_rn(0.5f);

    const int bi0 = blockIdx.x * TILES_PER_CTA;
    const int b   = bi0 >> 6;

    // prologue: stage zs + fill d buffer 0
    {
        const float* dptr = dists + (size_t)bi0 * (N_PART * BASIS);
        for (int idx = tid; idx < N_PART * (BASIS / 2); idx += 256) {
            int j = idx >> 4, q = idx & 15;
            float2 v = *(const float2*)(dptr + j * BASIS + q * 2);
            d_sw0[j * DPADW + q] = pack_h2(v.x, v.y);
        }
        const float* zsb = g_zs + (size_t)b * (N_PART * KDIM);
        for (int idx = tid; idx < (N_PART * KDIM) / 4; idx += 256) {
            int j = idx >> 5, q = idx & 31;
            float4 v = *(const float4*)(zsb + j * KDIM + q * 4);
            *(float4*)&zs_s[j * ZPAD + q * 4] = v;
        }
    }
    __syncthreads();

#pragma unroll 1
    for (int t = 0; t < TILES_PER_CTA; ++t) {
        const int bi = bi0 + t;
        const int i  = bi & 63;
        const uint32_t ldsm_d = (t & 1) ? ldsm_d1 : ldsm_d0;

        // ---- GEMM1: fp16 acc, 5 LDSM4, 20 mma ----
        uint32_t c1[2][5][2];
#pragma unroll
        for (int mt = 0; mt < 2; ++mt)
#pragma unroll
            for (int nt = 0; nt < 5; ++nt) { c1[mt][nt][0] = 0u; c1[mt][nt][1] = 0u; }
#pragma unroll
        for (int nt = 0; nt < 5; ++nt) {
            uint32_t r0, r1, r2, r3;
            LDSM4(r0, r1, r2, r3, ldsm_d + nt * (8 * DPADW * 4));
            mma_f16h(c1[0][nt], a1r[0][0], r0, r1);
            mma_f16h(c1[1][nt], a1r[0][1], r0, r1);
            mma_f16h(c1[0][nt], a1r[1][0], r2, r3);
            mma_f16h(c1[1][nt], a1r[1][1], r2, r3);
        }

        // ---- prefetch next tile's dists ----
        if (t + 1 < TILES_PER_CTA) {
            uint32_t* dnext = ((t + 1) & 1) ? d_sw1 : d_sw0;
            const float* dptr = dists + (size_t)(bi + 1) * (N_PART * BASIS);
            for (int idx = tid; idx < N_PART * (BASIS / 2); idx += 256) {
                int j = idx >> 4, q = idx & 15;
                float2 v = *(const float2*)(dptr + j * BASIS + q * 2);
                dnext[j * DPADW + q] = pack_h2(v.x, v.y);
            }
        }

        // ---- epilogue 1: h = ssp(D1 + kb1), half2 poly, 4 rows ----
#pragma unroll
        for (int nt = 0; nt < 5; ++nt) {
            const int j0 = jbase + nt * 8 + 2 * tg;
            const int j1 = j0 + 1;
#pragma unroll
            for (int mt = 0; mt < 2; ++mt) {
#pragma unroll
                for (int hh = 0; hh < 2; ++hh) {
                    const int row = mbase + mt * 16 + hh * 8 + g;
                    __half2 x = __hadd2(*(__half2*)&c1[mt][nt][hh], kb1h[mt * 2 + hh]);
                    __half2 y = __hmul2(x, HHALF);
                    __half2 v = __hmul2(y, y);
                    __half2 p = __hfma2(v, D5, D4);
                    p = __hfma2(v, p, D3);
                    p = __hfma2(v, p, D2);
                    p = __hfma2(v, p, D1);
                    __half2 hres = __hfma2(v, p, y);
                    h_sh[j0 * (2 * HPADW) + row] = __low2half(hres);
                    h_sh[j1 * (2 * HPADW) + row] = __high2half(hres);
                }
            }
        }
        __syncthreads();   // h ready; d reads complete

        // ---- GEMM2: fp16 acc, 20 LDSM4, 80 mma ----
        uint32_t c2[2][5][2];
#pragma unroll
        for (int mt = 0; mt < 2; ++mt)
#pragma unroll
            for (int nt = 0; nt < 5; ++nt) { c2[mt][nt][0] = 0u; c2[mt][nt][1] = 0u; }
#pragma unroll
        for (int kp = 0; kp < 8; kp += 2) {
#pragma unroll
            for (int nt = 0; nt < 5; ++nt) {
                uint32_t r0, r1, r2, r3;
                LDSM4(r0, r1, r2, r3, ldsm_h + nt * (8 * HPADW * 4) + kp * 32);
                mma_f16h(c2[0][nt], a2r[kp][0],     r0, r1);
                mma_f16h(c2[1][nt], a2r[kp][1],     r0, r1);
                mma_f16h(c2[0][nt], a2r[kp + 1][0], r2, r3);
                mma_f16h(c2[1][nt], a2r[kp + 1][1], r2, r3);
            }
        }

        // ---- epilogue 2: mask j==i, weight by zs, reduce over j ----
        float o[4] = {0.f, 0.f, 0.f, 0.f};
#pragma unroll
        for (int nt = 0; nt < 5; ++nt) {
            const int j0 = nt * 8 + 2 * tg + jbase;
            const int j1 = j0 + 1;
#pragma unroll
            for (int mt = 0; mt < 2; ++mt) {
                float2 flo = __half22float2(*(__half2*)&c2[mt][nt][0]);
                float2 fhi = __half22float2(*(__half2*)&c2[mt][nt][1]);
                const int rlo = mbase + mt * 16 + g;
                const int rhi = rlo + 8;
                if (j0 != i) {
                    o[mt * 2 + 0] = fmaf(flo.x + kb2v[mt * 2 + 0], zs_s[j0 * ZPAD + rlo], o[mt * 2 + 0]);
                    o[mt * 2 + 1] = fmaf(fhi.x + kb2v[mt * 2 + 1], zs_s[j0 * ZPAD + rhi], o[mt * 2 + 1]);
                }
                if (j1 != i) {
                    o[mt * 2 + 0] = fmaf(flo.y + kb2v[mt * 2 + 0], zs_s[j1 * ZPAD + rlo], o[mt * 2 + 0]);
                    o[mt * 2 + 1] = fmaf(fhi.y + kb2v[mt * 2 + 1], zs_s[j1 * ZPAD + rhi], o[mt * 2 + 1]);
                }
            }
        }
#pragma unroll
        for (int q = 0; q < 4; ++q) {
            o[q] += __shfl_xor_sync(0xFFFFFFFFu, o[q], 1);
            o[q] += __shfl_xor_sync(0xFFFFFFFFu, o[q], 2);
        }
        if (tg == 0) {
            float* rp = red + jg * 128;
            rp[ra0] = o[0];
            rp[ra1] = o[1];
            rp[rb0] = o[2];
            rp[rb1] = o[3];
        }
        __syncthreads();   // red ready; h free; prefetch visible

        if (tid < 128)
            g_zsout[(size_t)bi * KDIM + tid] = red[tid] + red[128 + tid];
        // next epi2's red writes are fenced by next iteration's first sync
    }
}

// ---------------------------------------------------------------------------
extern "C" void kernel_launch(void* const* d_in, const int* in_sizes, int n_in,
                              void* d_out, int out_size) {
    const float* dists = (const float*)d_in[0];
    const float* emb_e = (const float*)d_in[1];
    const float* emb_n = (const float*)d_in[2];
    const float* kW1   = (const float*)d_in[3];
    const float* kb1   = (const float*)d_in[4];
    const float* kW2   = (const float*)d_in[5];
    const float* kb2   = (const float*)d_in[6];
    const float* eiW   = (const float*)d_in[7];
    const float* eoW1  = (const float*)d_in[8];
    const float* eob1  = (const float*)d_in[9];
    const float* eoW2  = (const float*)d_in[10];
    const float* eob2  = (const float*)d_in[11];
    float* xs = (float*)d_out;

    const int cf_smem = SMEM_WORDS * 4;                    // 77824 B
    const int oz_smem = (4 * 128 * ASTR + 256) * 4;        // 140288 B
    cudaFuncSetAttribute(cfconv_mma_kernel,
                         cudaFuncAttributeMaxDynamicSharedMemorySize, cf_smem);
    cudaFuncSetAttribute(outzs_mma_kernel,
                         cudaFuncAttributeMaxDynamicSharedMemorySize, oz_smem);

    z0_kernel<<<1, 128>>>(emb_e, eiW);
    fill0_kernel<<<(BSZ * N_PART * KDIM + 255) / 256, 256>>>(emb_e, emb_n, xs);

    for (int l = 0; l < LAYERS; ++l) {
        cfconv_mma_kernel<<<CFC_GRID, 256, cf_smem>>>(dists,
                                    kW1 + (size_t)l * BASIS * KDIM,
                                    kb1 + (size_t)l * KDIM,
                                    kW2 + (size_t)l * KDIM * KDIM,
                                    kb2 + (size_t)l * KDIM);
        const float* eiW_next = (l + 1 < LAYERS)
                              ? eiW + (size_t)(l + 1) * DDIM * KDIM : nullptr;
        outzs_mma_kernel<<<NBI / 128, 256, oz_smem>>>(
                                     eoW1 + (size_t)l * KDIM * DDIM,
                                     eob1 + (size_t)l * DDIM,
                                     eoW2 + (size_t)l * DDIM * DDIM,
                                     eob2 + (size_t)l * DDIM,
                                     eiW_next,
                                     xs);
    }
}

// round 16
// speedup vs baseline: 1.0724x; 1.0724x over previous
#include <cuda_runtime.h>
#include <cuda_fp16.h>
#include <math.h>
#include <stdint.h>

#define N_ELEC 64
#define N_NUC  16
#define N_PART 80
#define BASIS  32
#define KDIM   128
#define DDIM   128
#define BSZ    256
#define LAYERS 3
#define NBI    (BSZ * N_ELEC)

#define TILES_PER_CTA 8
#define CFC_GRID (NBI / TILES_PER_CTA)

// cfconv SMEM word-layout (4-byte words): two d buffers, h, zs  (R13 exact)
#define DPADW 20
#define HPADW 68
#define ZPAD  132
#define DBUF_WORDS (N_PART * DPADW)                 // 1600
#define OFF_H   (2 * DBUF_WORDS)                    // 3200
#define OFF_ZS  (OFF_H + N_PART * HPADW)            // 8640
#define SMEM_WORDS (OFF_ZS + N_PART * ZPAD)         // 19200 words = 76800 B

// outzs SMEM layout (words)
#define ASTR 68
#define OZ_BUF0 0
#define OZ_BUF1 (128 * ASTR)                        // 8704
#define OZ_AW   (2 * 128 * ASTR)                    // 17408
#define OZ_BIAS (OZ_AW + 64 * ASTR)                 // 21760
#define OZ_WORDS (OZ_BIAS + 256)                    // 22016 words = 88064 B

// Scratch (no cudaMalloc allowed)
__device__ float g_zs[BSZ * N_PART * KDIM];      // (b, j, k)
__device__ float g_zsout[BSZ * N_ELEC * KDIM];   // cfconv output
__device__ float g_zrow[2 * KDIM];               // layer-0 zs rows (up, dn)

__device__ __forceinline__ float ssp_f(float x) {
    float ax = fabsf(x);
    return fmaxf(x, 0.0f) + __logf(1.0f + __expf(-ax)) - 0.69314718055994530942f;
}

__device__ __forceinline__ uint32_t pack_h2(float lo, float hi) {
    __half2 h = __floats2half2_rn(lo, hi);
    return *(uint32_t*)&h;
}

__device__ __forceinline__ uint32_t smem_u32(const void* p) {
    uint32_t a;
    asm("{ .reg .u64 t; cvta.to.shared.u64 t, %1; cvt.u32.u64 %0, t; }" : "=r"(a) : "l"(p));
    return a;
}

// m16n8k16 fp16 mma, fp32 accumulate (baseline PTX, sm_80+)
__device__ __forceinline__ void mma_f16(float* d, const uint32_t* a,
                                        uint32_t b0, uint32_t b1) {
    asm volatile(
        "mma.sync.aligned.m16n8k16.row.col.f32.f16.f16.f32 "
        "{%0,%1,%2,%3}, {%4,%5,%6,%7}, {%8,%9}, {%0,%1,%2,%3};"
        : "+f"(d[0]), "+f"(d[1]), "+f"(d[2]), "+f"(d[3])
        : "r"(a[0]), "r"(a[1]), "r"(a[2]), "r"(a[3]), "r"(b0), "r"(b1));
}

// ldmatrix x4 (sm_75+ baseline PTX)
#define LDSM4(r0, r1, r2, r3, addr) \
    asm volatile("ldmatrix.sync.aligned.m8n8.x4.shared.b16 {%0,%1,%2,%3}, [%4];" \
                 : "=r"(r0), "=r"(r1), "=r"(r2), "=r"(r3) : "r"(addr))

// ---------------------------------------------------------------------------
__global__ void z0_kernel(const float* __restrict__ emb_e,
                          const float* __restrict__ eiW) {
    __shared__ float eup[DDIM], edn[DDIM];
    int k = threadIdx.x;
    eup[k] = emb_e[k];
    edn[k] = emb_e[N_ELEC / 2 * DDIM + k];
    __syncthreads();
    float au = 0.f, ad = 0.f;
#pragma unroll 4
    for (int d = 0; d < DDIM; ++d) {
        float w = eiW[d * KDIM + k];
        au = fmaf(eup[d], w, au);
        ad = fmaf(edn[d], w, ad);
    }
    g_zrow[k] = au;
    g_zrow[KDIM + k] = ad;
}

__global__ void fill0_kernel(const float* __restrict__ emb_e,
                             const float* __restrict__ emb_n,
                             float* __restrict__ xs) {
    int idx = blockIdx.x * blockDim.x + threadIdx.x;
    if (idx < BSZ * N_PART * KDIM) {
        int jk = idx % (N_PART * KDIM);
        int j = jk >> 7, k = jk & 127;
        float v;
        if (j < N_ELEC) v = g_zrow[(j >= N_ELEC / 2 ? KDIM : 0) + k];
        else            v = emb_n[(j - N_ELEC) * KDIM + k];
        g_zs[idx] = v;
    }
    if (idx < BSZ * N_ELEC * DDIM) {
        xs[idx] = emb_e[idx % (N_ELEC * DDIM)];
    }
}

// ---------------------------------------------------------------------------
// Fused output MLP + next-layer zs — phased weights, 64 rows/CTA, 2 CTAs/SM.
//   grid = NBI/64 = 256. Warp (wg, nh): wg = wid>>1 owns rows wg*16..+15,
//   nh = wid&1 owns n-tiles nh*8..nh*8+7.
// ---------------------------------------------------------------------------
extern __shared__ uint32_t dyn_smem_w[];

__global__ void __launch_bounds__(256, 2) outzs_mma_kernel(
    const float* __restrict__ eoW1, const float* __restrict__ eob1,
    const float* __restrict__ eoW2, const float* __restrict__ eob2,
    const float* __restrict__ eiW_next,   // may be nullptr (last layer)
    float* __restrict__ xs)
{
    uint32_t* buf0 = dyn_smem_w + OZ_BUF0;   // eoW1^T -> later eiW^T
    uint32_t* buf1 = dyn_smem_w + OZ_BUF1;   // eoW2^T
    uint32_t* a_w  = dyn_smem_w + OZ_AW;     // 64 rows: zsout -> T -> xs_new
    float*    bias = (float*)(dyn_smem_w + OZ_BIAS);

    const int tid  = threadIdx.x;
    const int wid  = tid >> 5;
    const int lane = tid & 31;
    const int g    = lane >> 2;
    const int tg   = lane & 3;
    const int wg   = wid >> 1;              // row group 0..3
    const int nh   = wid & 1;               // n half 0..1
    const int rblk = blockIdx.x * 64;
    const int r0   = wg * 16 + g;           // local row (0..63)

    // stage eoW1^T -> buf0, zsout rows -> a_w, biases
    for (int idx = tid; idx < 128 * 64; idx += 256) {
        int kp = idx >> 7, d = idx & 127;
        buf0[d * ASTR + kp] = pack_h2(eoW1[(2 * kp) * DDIM + d],
                                      eoW1[(2 * kp + 1) * DDIM + d]);
    }
    for (int idx = tid; idx < 64 * 64; idx += 256) {
        int r = idx >> 6, kw = idx & 63;
        float2 v = *(const float2*)&g_zsout[(size_t)(rblk + r) * KDIM + kw * 2];
        a_w[r * ASTR + kw] = pack_h2(v.x, v.y);
    }
    if (tid < 128) { bias[tid] = eob1[tid]; bias[128 + tid] = eob2[tid]; }
    __syncthreads();

    // load eoW2^T -> buf1 (overlaps GEMM1)
    for (int idx = tid; idx < 128 * 64; idx += 256) {
        int kp = idx >> 7, d = idx & 127;
        buf1[d * ASTR + kp] = pack_h2(eoW2[(2 * kp) * DDIM + d],
                                      eoW2[(2 * kp + 1) * DDIM + d]);
    }

    float acc[8][4];
#pragma unroll
    for (int nt = 0; nt < 8; ++nt) {
        acc[nt][0] = 0.f; acc[nt][1] = 0.f; acc[nt][2] = 0.f; acc[nt][3] = 0.f;
    }
    // GEMM1: zsout @ eoW1 (this warp: 16 rows x 64 n-cols)
#pragma unroll
    for (int kk = 0; kk < 8; ++kk) {
        uint32_t a[4];
        int ab = r0 * ASTR + kk * 8 + tg;
        a[0] = a_w[ab];
        a[1] = a_w[ab + 8 * ASTR];
        a[2] = a_w[ab + 4];
        a[3] = a_w[ab + 8 * ASTR + 4];
#pragma unroll
        for (int nt = 0; nt < 8; ++nt) {
            int nb = ((nh * 8 + nt) * 8 + g) * ASTR + kk * 8 + tg;
            mma_f16(acc[nt], a, buf0[nb], buf0[nb + 4]);
        }
    }
    __syncthreads();   // GEMM1 reads done; buf1 visible

    // epilogue 1: T = ssp(C1 + eob1) into a_w
#pragma unroll
    for (int nt = 0; nt < 8; ++nt) {
        int ntg = nh * 8 + nt;
        int d0 = ntg * 8 + 2 * tg;
        float ba = bias[d0], bb = bias[d0 + 1];
        a_w[r0 * ASTR + ntg * 4 + tg] =
            pack_h2(ssp_f(acc[nt][0] + ba), ssp_f(acc[nt][1] + bb));
        a_w[(r0 + 8) * ASTR + ntg * 4 + tg] =
            pack_h2(ssp_f(acc[nt][2] + ba), ssp_f(acc[nt][3] + bb));
        acc[nt][0] = 0.f; acc[nt][1] = 0.f; acc[nt][2] = 0.f; acc[nt][3] = 0.f;
    }
    __syncthreads();

    // load eiW_next^T -> buf0 (overlaps GEMM2)
    if (eiW_next) {
        for (int idx = tid; idx < 128 * 64; idx += 256) {
            int kp = idx >> 7, d = idx & 127;
            buf0[d * ASTR + kp] = pack_h2(eiW_next[(2 * kp) * KDIM + d],
                                          eiW_next[(2 * kp + 1) * KDIM + d]);
        }
    }

    // GEMM2: T @ eoW2
#pragma unroll
    for (int kk = 0; kk < 8; ++kk) {
        uint32_t a[4];
        int ab = r0 * ASTR + kk * 8 + tg;
        a[0] = a_w[ab];
        a[1] = a_w[ab + 8 * ASTR];
        a[2] = a_w[ab + 4];
        a[3] = a_w[ab + 8 * ASTR + 4];
#pragma unroll
        for (int nt = 0; nt < 8; ++nt) {
            int nb = ((nh * 8 + nt) * 8 + g) * ASTR + kk * 8 + tg;
            mma_f16(acc[nt], a, buf1[nb], buf1[nb + 4]);
        }
    }
    __syncthreads();   // GEMM2 reads of a_w done; buf0 (eiW) visible

    // epilogue 2: xs_new = xs + C2 + eob2; write xs; stash fp16 in a_w
    float* x0 = xs + (size_t)(rblk + r0) * DDIM;
    float* x1 = xs + (size_t)(rblk + r0 + 8) * DDIM;
#pragma unroll
    for (int nt = 0; nt < 8; ++nt) {
        int ntg = nh * 8 + nt;
        int d0 = ntg * 8 + 2 * tg;
        float ba = bias[128 + d0], bb = bias[128 + d0 + 1];
        float2 v0 = *(float2*)&x0[d0];
        float2 v1 = *(float2*)&x1[d0];
        v0.x += acc[nt][0] + ba;  v0.y += acc[nt][1] + bb;
        v1.x += acc[nt][2] + ba;  v1.y += acc[nt][3] + bb;
        *(float2*)&x0[d0] = v0;
        *(float2*)&x1[d0] = v1;
        if (eiW_next) {
            a_w[r0 * ASTR + ntg * 4 + tg]       = pack_h2(v0.x, v0.y);
            a_w[(r0 + 8) * ASTR + ntg * 4 + tg] = pack_h2(v1.x, v1.y);
        }
    }

    if (!eiW_next) return;
    __syncthreads();

    // GEMM3: xs_new @ eiW_next -> g_zs
#pragma unroll
    for (int nt = 0; nt < 8; ++nt) {
        acc[nt][0] = 0.f; acc[nt][1] = 0.f; acc[nt][2] = 0.f; acc[nt][3] = 0.f;
    }
#pragma unroll
    for (int kk = 0; kk < 8; ++kk) {
        uint32_t a[4];
        int ab = r0 * ASTR + kk * 8 + tg;
        a[0] = a_w[ab];
        a[1] = a_w[ab + 8 * ASTR];
        a[2] = a_w[ab + 4];
        a[3] = a_w[ab + 8 * ASTR + 4];
#pragma unroll
        for (int nt = 0; nt < 8; ++nt) {
            int nb = ((nh * 8 + nt) * 8 + g) * ASTR + kk * 8 + tg;
            mma_f16(acc[nt], a, buf0[nb], buf0[nb + 4]);
        }
    }
    // all 64 rows of this CTA share the same batch index (64 | rblk)
    const int b  = rblk >> 6;
    float* z0p = g_zs + ((size_t)b * N_PART + r0) * KDIM;
    float* z1p = g_zs + ((size_t)b * N_PART + r0 + 8) * KDIM;
#pragma unroll
    for (int nt = 0; nt < 8; ++nt) {
        int k0 = (nh * 8 + nt) * 8 + 2 * tg;
        *(float2*)&z0p[k0] = make_float2(acc[nt][0], acc[nt][1]);
        *(float2*)&z1p[k0] = make_float2(acc[nt][2], acc[nt][3]);
    }
}

// ---------------------------------------------------------------------------
// cfconv: R13 exact (double-buffered d_s with prefetch, fp32 acc, half2 ssp)
// ---------------------------------------------------------------------------
__global__ void __launch_bounds__(256, 2) cfconv_mma_kernel(
    const float* __restrict__ dists,
    const float* __restrict__ kW1, const float* __restrict__ kb1,
    const float* __restrict__ kW2, const float* __restrict__ kb2)
{
    uint32_t* d_sw0 = dyn_smem_w;
    uint32_t* d_sw1 = dyn_smem_w + DBUF_WORDS;
    __half*   h_sh  = (__half*)(dyn_smem_w + OFF_H);
    float*    zs_s  = (float*)(dyn_smem_w + OFF_ZS);
    uint32_t* h_sw  = dyn_smem_w + OFF_H;

    const int tid  = threadIdx.x;
    const int wid  = tid >> 5;
    const int lane = tid & 31;
    const int g    = lane >> 2;
    const int tg   = lane & 3;
    const int m0   = wid * 16 + g;
    const int m1   = m0 + 8;

    const int role = lane >> 3;
    const int rrow = lane & 7;
    const uint32_t ldsm_off = rrow * (DPADW * 4) + (role >> 1) * 32 + (role & 1) * 16;
    const uint32_t ldsm_d0 = smem_u32(d_sw0) + ldsm_off;
    const uint32_t ldsm_d1 = smem_u32(d_sw1) + ldsm_off;
    const uint32_t ldsm_h  = smem_u32(h_sw) + rrow * (HPADW * 4)
                           + (role >> 1) * 32 + (role & 1) * 16;

    uint32_t a1r[2][4];
#pragma unroll
    for (int kk = 0; kk < 2; ++kk) {
        int f = kk * 16 + 2 * tg;
        a1r[kk][0] = pack_h2(kW1[f * KDIM + m0],       kW1[(f + 1) * KDIM + m0]);
        a1r[kk][1] = pack_h2(kW1[f * KDIM + m1],       kW1[(f + 1) * KDIM + m1]);
        a1r[kk][2] = pack_h2(kW1[(f + 8) * KDIM + m0], kW1[(f + 9) * KDIM + m0]);
        a1r[kk][3] = pack_h2(kW1[(f + 8) * KDIM + m1], kW1[(f + 9) * KDIM + m1]);
    }
    uint32_t a2r[8][4];
#pragma unroll
    for (int kk = 0; kk < 8; ++kk) {
        int mm = kk * 16 + 2 * tg;
        a2r[kk][0] = pack_h2(kW2[mm * KDIM + m0],       kW2[(mm + 1) * KDIM + m0]);
        a2r[kk][1] = pack_h2(kW2[mm * KDIM + m1],       kW2[(mm + 1) * KDIM + m1]);
        a2r[kk][2] = pack_h2(kW2[(mm + 8) * KDIM + m0], kW2[(mm + 9) * KDIM + m0]);
        a2r[kk][3] = pack_h2(kW2[(mm + 8) * KDIM + m1], kW2[(mm + 9) * KDIM + m1]);
    }
    const __half2 kb1a2 = __half2half2(__float2half_rn(kb1[m0]));
    const __half2 kb1b2 = __half2half2(__float2half_rn(kb1[m1]));
    const float kb2a = kb2[m0], kb2b = kb2[m1];

    const __half2 D1 = __float2half2_rn( 0.5f);
    const __half2 D2 = __float2half2_rn(-8.3333333e-2f);
    const __half2 D3 = __float2half2_rn( 2.2222222e-2f);
    const __half2 D4 = __float2half2_rn(-6.7460317e-3f);
    const __half2 D5 = __float2half2_rn( 2.1869489e-3f);
    const __half2 HHALF = __float2half2_rn(0.5f);

    const int bi0 = blockIdx.x * TILES_PER_CTA;
    const int b   = bi0 >> 6;

    {
        const float* dptr = dists + (size_t)bi0 * (N_PART * BASIS);
        for (int idx = tid; idx < N_PART * (BASIS / 2); idx += 256) {
            int j = idx >> 4, q = idx & 15;
            float2 v = *(const float2*)(dptr + j * BASIS + q * 2);
            d_sw0[j * DPADW + q] = pack_h2(v.x, v.y);
        }
        const float* zsb = g_zs + (size_t)b * (N_PART * KDIM);
        for (int idx = tid; idx < (N_PART * KDIM) / 4; idx += 256) {
            int j = idx >> 5, q = idx & 31;
            float4 v = *(const float4*)(zsb + j * KDIM + q * 4);
            *(float4*)&zs_s[j * ZPAD + q * 4] = v;
        }
    }
    __syncthreads();

#pragma unroll 1
    for (int t = 0; t < TILES_PER_CTA; ++t) {
        const int bi = bi0 + t;
        const int i  = bi & 63;
        const uint32_t ldsm_d = (t & 1) ? ldsm_d1 : ldsm_d0;

        float acc[10][4];
#pragma unroll
        for (int nt = 0; nt < 10; ++nt) {
            acc[nt][0] = 0.0f; acc[nt][1] = 0.0f;
            acc[nt][2] = 0.0f; acc[nt][3] = 0.0f;
        }
#pragma unroll
        for (int nt = 0; nt < 10; ++nt) {
            uint32_t r0, r1, r2, r3;
            LDSM4(r0, r1, r2, r3, ldsm_d + nt * (8 * DPADW * 4));
            mma_f16(acc[nt], a1r[0], r0, r1);
            mma_f16(acc[nt], a1r[1], r2, r3);
        }

        if (t + 1 < TILES_PER_CTA) {
            uint32_t* dnext = ((t + 1) & 1) ? d_sw1 : d_sw0;
            const float* dptr = dists + (size_t)(bi + 1) * (N_PART * BASIS);
            for (int idx = tid; idx < N_PART * (BASIS / 2); idx += 256) {
                int j = idx >> 4, q = idx & 15;
                float2 v = *(const float2*)(dptr + j * BASIS + q * 2);
                dnext[j * DPADW + q] = pack_h2(v.x, v.y);
            }
        }

#pragma unroll
        for (int nt = 0; nt < 10; ++nt) {
            const int j0 = nt * 8 + 2 * tg;
            const int j1 = j0 + 1;
            __half2 x01 = __hadd2(__floats2half2_rn(acc[nt][0], acc[nt][1]), kb1a2);
            __half2 x23 = __hadd2(__floats2half2_rn(acc[nt][2], acc[nt][3]), kb1b2);
            __half2 y01 = __hmul2(x01, HHALF);
            __half2 y23 = __hmul2(x23, HHALF);
            __half2 v01 = __hmul2(y01, y01);
            __half2 v23 = __hmul2(y23, y23);
            __half2 p01 = __hfma2(v01, D5, D4);
            __half2 p23 = __hfma2(v23, D5, D4);
            p01 = __hfma2(v01, p01, D3);  p23 = __hfma2(v23, p23, D3);
            p01 = __hfma2(v01, p01, D2);  p23 = __hfma2(v23, p23, D2);
            p01 = __hfma2(v01, p01, D1);  p23 = __hfma2(v23, p23, D1);
            __half2 h01 = __hfma2(v01, p01, y01);
            __half2 h23 = __hfma2(v23, p23, y23);
            h_sh[j0 * (2 * HPADW) + m0] = __low2half(h01);
            h_sh[j1 * (2 * HPADW) + m0] = __high2half(h01);
            h_sh[j0 * (2 * HPADW) + m1] = __low2half(h23);
            h_sh[j1 * (2 * HPADW) + m1] = __high2half(h23);
        }
        __syncthreads();

#pragma unroll
        for (int nt = 0; nt < 10; ++nt) {
            acc[nt][0] = 0.0f; acc[nt][1] = 0.0f;
            acc[nt][2] = 0.0f; acc[nt][3] = 0.0f;
        }
#pragma unroll
        for (int kp = 0; kp < 8; kp += 2) {
#pragma unroll
            for (int nt = 0; nt < 10; ++nt) {
                uint32_t r0, r1, r2, r3;
                LDSM4(r0, r1, r2, r3, ldsm_h + nt * (8 * HPADW * 4) + kp * 32);
                mma_f16(acc[nt], a2r[kp],     r0, r1);
                mma_f16(acc[nt], a2r[kp + 1], r2, r3);
            }
        }

        float o0 = 0.0f, o1 = 0.0f;
#pragma unroll
        for (int nt = 0; nt < 10; ++nt) {
            const int j0 = nt * 8 + 2 * tg;
            const int j1 = j0 + 1;
            const float w00 = acc[nt][0] + kb2a;
            const float w01 = acc[nt][1] + kb2a;
            const float w10 = acc[nt][2] + kb2b;
            const float w11 = acc[nt][3] + kb2b;
            if (j0 != i) {
                o0 = fmaf(w00, zs_s[j0 * ZPAD + m0], o0);
                o1 = fmaf(w10, zs_s[j0 * ZPAD + m1], o1);
            }
            if (j1 != i) {
                o0 = fmaf(w01, zs_s[j1 * ZPAD + m0], o0);
                o1 = fmaf(w11, zs_s[j1 * ZPAD + m1], o1);
            }
        }
        o0 += __shfl_xor_sync(0xFFFFFFFFu, o0, 1);
        o0 += __shfl_xor_sync(0xFFFFFFFFu, o0, 2);
        o1 += __shfl_xor_sync(0xFFFFFFFFu, o1, 1);
        o1 += __shfl_xor_sync(0xFFFFFFFFu, o1, 2);
        if (tg == 0) {
            g_zsout[(size_t)bi * KDIM + m0] = o0;
            g_zsout[(size_t)bi * KDIM + m1] = o1;
        }
        __syncthreads();
    }
}

// ---------------------------------------------------------------------------
extern "C" void kernel_launch(void* const* d_in, const int* in_sizes, int n_in,
                              void* d_out, int out_size) {
    const float* dists = (const float*)d_in[0];
    const float* emb_e = (const float*)d_in[1];
    const float* emb_n = (const float*)d_in[2];
    const float* kW1   = (const float*)d_in[3];
    const float* kb1   = (const float*)d_in[4];
    const float* kW2   = (const float*)d_in[5];
    const float* kb2   = (const float*)d_in[6];
    const float* eiW   = (const float*)d_in[7];
    const float* eoW1  = (const float*)d_in[8];
    const float* eob1  = (const float*)d_in[9];
    const float* eoW2  = (const float*)d_in[10];
    const float* eob2  = (const float*)d_in[11];
    float* xs = (float*)d_out;

    const int cf_smem = SMEM_WORDS * 4;    // 76800 B
    const int oz_smem = OZ_WORDS * 4;      // 88064 B
    cudaFuncSetAttribute(cfconv_mma_kernel,
                         cudaFuncAttributeMaxDynamicSharedMemorySize, cf_smem);
    cudaFuncSetAttribute(outzs_mma_kernel,
                         cudaFuncAttributeMaxDynamicSharedMemorySize, oz_smem);

    z0_kernel<<<1, 128>>>(emb_e, eiW);
    fill0_kernel<<<(BSZ * N_PART * KDIM + 255) / 256, 256>>>(emb_e, emb_n, xs);

    for (int l = 0; l < LAYERS; ++l) {
        cfconv_mma_kernel<<<CFC_GRID, 256, cf_smem>>>(dists,
                                    kW1 + (size_t)l * BASIS * KDIM,
                                    kb1 + (size_t)l * KDIM,
                                    kW2 + (size_t)l * KDIM * KDIM,
                                    kb2 + (size_t)l * KDIM);
        const float* eiW_next = (l + 1 < LAYERS)
                              ? eiW + (size_t)(l + 1) * DDIM * KDIM : nullptr;
        outzs_mma_kernel<<<NBI / 64, 256, oz_smem>>>(
                                     eoW1 + (size_t)l * KDIM * DDIM,
                                     eob1 + (size_t)l * DDIM,
                                     eoW2 + (size_t)l * DDIM * DDIM,
                                     eob2 + (size_t)l * DDIM,
                                     eiW_next,
                                     xs);
    }
}

// round 17
// speedup vs baseline: 1.0770x; 1.0044x over previous
#include <cuda_runtime.h>
#include <cuda_fp16.h>
#include <math.h>
#include <stdint.h>

#define N_ELEC 64
#define N_NUC  16
#define N_PART 80
#define BASIS  32
#define KDIM   128
#define DDIM   128
#define BSZ    256
#define LAYERS 3
#define NBI    (BSZ * N_ELEC)

#define TILES_PER_CTA 8
#define CFC_GRID (NBI / TILES_PER_CTA)

// cfconv SMEM word-layout (4-byte words): two d buffers, h, zs  (R13 exact)
#define DPADW 20
#define HPADW 68
#define ZPAD  132
#define DBUF_WORDS (N_PART * DPADW)                 // 1600
#define OFF_H   (2 * DBUF_WORDS)                    // 3200
#define OFF_ZS  (OFF_H + N_PART * HPADW)            // 8640
#define SMEM_WORDS (OFF_ZS + N_PART * ZPAD)         // 19200 words = 76800 B

// side-kernel SMEM row stride (words)
#define ASTR 68

// Scratch (no cudaMalloc allowed)
__device__ float g_zs[BSZ * N_PART * KDIM];      // (b, j, k)
__device__ float g_zsout[BSZ * N_ELEC * KDIM];   // cfconv output
__device__ float g_zrow[2 * KDIM];               // layer-0 zs rows (up, dn)

__device__ __forceinline__ float ssp_f(float x) {
    float ax = fabsf(x);
    return fmaxf(x, 0.0f) + __logf(1.0f + __expf(-ax)) - 0.69314718055994530942f;
}

__device__ __forceinline__ uint32_t pack_h2(float lo, float hi) {
    __half2 h = __floats2half2_rn(lo, hi);
    return *(uint32_t*)&h;
}

__device__ __forceinline__ uint32_t smem_u32(const void* p) {
    uint32_t a;
    asm("{ .reg .u64 t; cvta.to.shared.u64 t, %1; cvt.u32.u64 %0, t; }" : "=r"(a) : "l"(p));
    return a;
}

// m16n8k16 fp16 mma, fp32 accumulate (baseline PTX, sm_80+)
__device__ __forceinline__ void mma_f16(float* d, const uint32_t* a,
                                        uint32_t b0, uint32_t b1) {
    asm volatile(
        "mma.sync.aligned.m16n8k16.row.col.f32.f16.f16.f32 "
        "{%0,%1,%2,%3}, {%4,%5,%6,%7}, {%8,%9}, {%0,%1,%2,%3};"
        : "+f"(d[0]), "+f"(d[1]), "+f"(d[2]), "+f"(d[3])
        : "r"(a[0]), "r"(a[1]), "r"(a[2]), "r"(a[3]), "r"(b0), "r"(b1));
}

// ldmatrix x4 (sm_75+ baseline PTX)
#define LDSM4(r0, r1, r2, r3, addr) \
    asm volatile("ldmatrix.sync.aligned.m8n8.x4.shared.b16 {%0,%1,%2,%3}, [%4];" \
                 : "=r"(r0), "=r"(r1), "=r"(r2), "=r"(r3) : "r"(addr))

// ---------------------------------------------------------------------------
// Layer-0 zs: xs rows are e_up / e_dn -> only 2 distinct zs rows. 1 block.
// ---------------------------------------------------------------------------
__global__ void z0_kernel(const float* __restrict__ emb_e,
                          const float* __restrict__ eiW) {
    __shared__ float eup[DDIM], edn[DDIM];
    int k = threadIdx.x;
    eup[k] = emb_e[k];
    edn[k] = emb_e[N_ELEC / 2 * DDIM + k];
    __syncthreads();
    float au = 0.f, ad = 0.f;
#pragma unroll 4
    for (int d = 0; d < DDIM; ++d) {
        float w = eiW[d * KDIM + k];
        au = fmaf(eup[d], w, au);
        ad = fmaf(edn[d], w, ad);
    }
    g_zrow[k] = au;
    g_zrow[KDIM + k] = ad;
}

// ---------------------------------------------------------------------------
// Fill: xs <- emb_e broadcast; g_zs NUC rows <- emb_n (electron rows are
// never read from g_zs: layer 0 stages from g_zrow, layers 1/2 use GEMM3's
// overwrite).
// ---------------------------------------------------------------------------
__global__ void fill0_kernel(const float* __restrict__ emb_e,
                             const float* __restrict__ emb_n,
                             float* __restrict__ xs) {
    int idx = blockIdx.x * blockDim.x + threadIdx.x;
    const int total_n = BSZ * N_NUC * KDIM;
    if (idx < total_n) {
        int b = idx / (N_NUC * KDIM);
        int r = idx % (N_NUC * KDIM);
        g_zs[(size_t)b * (N_PART * KDIM) + N_ELEC * KDIM + r] = emb_n[r];
    }
    if (idx < BSZ * N_ELEC * DDIM) {
        xs[idx] = emb_e[idx % (N_ELEC * DDIM)];
    }
}

// ---------------------------------------------------------------------------
// Fused output MLP + next-layer zs (R13 exact version: 128 rows/CTA)
// ---------------------------------------------------------------------------
extern __shared__ uint32_t dyn_smem_w[];

__global__ void __launch_bounds__(256) outzs_mma_kernel(
    const float* __restrict__ eoW1, const float* __restrict__ eob1,
    const float* __restrict__ eoW2, const float* __restrict__ eob2,
    const float* __restrict__ eiW_next,   // may be nullptr (last layer)
    float* __restrict__ xs)
{
    uint32_t* w1_w = dyn_smem_w;
    uint32_t* w2_w = dyn_smem_w + 128 * ASTR;
    uint32_t* a_w  = dyn_smem_w + 2 * 128 * ASTR;
    uint32_t* ei_w = dyn_smem_w + 3 * 128 * ASTR;
    float*    bias = (float*)(dyn_smem_w + 4 * 128 * ASTR);

    const int tid  = threadIdx.x;
    const int wid  = tid >> 5;
    const int lane = tid & 31;
    const int g    = lane >> 2;
    const int tg   = lane & 3;
    const int rblk = blockIdx.x * 128;
    const int r0   = wid * 16 + g;

    for (int idx = tid; idx < 128 * 64; idx += 256) {
        int kp = idx >> 7, d = idx & 127;
        w1_w[d * ASTR + kp] = pack_h2(eoW1[(2 * kp) * DDIM + d],
                                      eoW1[(2 * kp + 1) * DDIM + d]);
        w2_w[d * ASTR + kp] = pack_h2(eoW2[(2 * kp) * DDIM + d],
                                      eoW2[(2 * kp + 1) * DDIM + d]);
        if (eiW_next)
            ei_w[d * ASTR + kp] = pack_h2(eiW_next[(2 * kp) * KDIM + d],
                                          eiW_next[(2 * kp + 1) * KDIM + d]);
    }
    for (int idx = tid; idx < 128 * 64; idx += 256) {
        int r = idx >> 6, kw = idx & 63;
        float2 v = *(const float2*)&g_zsout[(size_t)(rblk + r) * KDIM + kw * 2];
        a_w[r * ASTR + kw] = pack_h2(v.x, v.y);
    }
    if (tid < 128) { bias[tid] = eob1[tid]; bias[128 + tid] = eob2[tid]; }
    __syncthreads();

    float acc[16][4];
#pragma unroll
    for (int nt = 0; nt < 16; ++nt) {
        acc[nt][0] = 0.f; acc[nt][1] = 0.f; acc[nt][2] = 0.f; acc[nt][3] = 0.f;
    }
#pragma unroll
    for (int kk = 0; kk < 8; ++kk) {
        uint32_t a[4];
        int ab = r0 * ASTR + kk * 8 + tg;
        a[0] = a_w[ab];
        a[1] = a_w[ab + 8 * ASTR];
        a[2] = a_w[ab + 4];
        a[3] = a_w[ab + 8 * ASTR + 4];
#pragma unroll
        for (int nt = 0; nt < 16; ++nt) {
            int nb = (nt * 8 + g) * ASTR + kk * 8 + tg;
            mma_f16(acc[nt], a, w1_w[nb], w1_w[nb + 4]);
        }
    }
    __syncthreads();

#pragma unroll
    for (int nt = 0; nt < 16; ++nt) {
        int d0 = nt * 8 + 2 * tg;
        float ba = bias[d0], bb = bias[d0 + 1];
        w1_w[r0 * ASTR + nt * 4 + tg] =
            pack_h2(ssp_f(acc[nt][0] + ba), ssp_f(acc[nt][1] + bb));
        w1_w[(r0 + 8) * ASTR + nt * 4 + tg] =
            pack_h2(ssp_f(acc[nt][2] + ba), ssp_f(acc[nt][3] + bb));
        acc[nt][0] = 0.f; acc[nt][1] = 0.f; acc[nt][2] = 0.f; acc[nt][3] = 0.f;
    }
    __syncthreads();

#pragma unroll
    for (int kk = 0; kk < 8; ++kk) {
        uint32_t a[4];
        int ab = r0 * ASTR + kk * 8 + tg;
        a[0] = w1_w[ab];
        a[1] = w1_w[ab + 8 * ASTR];
        a[2] = w1_w[ab + 4];
        a[3] = w1_w[ab + 8 * ASTR + 4];
#pragma unroll
        for (int nt = 0; nt < 16; ++nt) {
            int nb = (nt * 8 + g) * ASTR + kk * 8 + tg;
            mma_f16(acc[nt], a, w2_w[nb], w2_w[nb + 4]);
        }
    }

    float* x0 = xs + (size_t)(rblk + r0) * DDIM;
    float* x1 = xs + (size_t)(rblk + r0 + 8) * DDIM;
#pragma unroll
    for (int nt = 0; nt < 16; ++nt) {
        int d0 = nt * 8 + 2 * tg;
        float ba = bias[128 + d0], bb = bias[128 + d0 + 1];
        float2 v0 = *(float2*)&x0[d0];
        float2 v1 = *(float2*)&x1[d0];
        v0.x += acc[nt][0] + ba;  v0.y += acc[nt][1] + bb;
        v1.x += acc[nt][2] + ba;  v1.y += acc[nt][3] + bb;
        *(float2*)&x0[d0] = v0;
        *(float2*)&x1[d0] = v1;
        if (eiW_next) {
            a_w[r0 * ASTR + nt * 4 + tg]       = pack_h2(v0.x, v0.y);
            a_w[(r0 + 8) * ASTR + nt * 4 + tg] = pack_h2(v1.x, v1.y);
        }
    }

    if (!eiW_next) return;
    __syncthreads();

#pragma unroll
    for (int nt = 0; nt < 16; ++nt) {
        acc[nt][0] = 0.f; acc[nt][1] = 0.f; acc[nt][2] = 0.f; acc[nt][3] = 0.f;
    }
#pragma unroll
    for (int kk = 0; kk < 8; ++kk) {
        uint32_t a[4];
        int ab = r0 * ASTR + kk * 8 + tg;
        a[0] = a_w[ab];
        a[1] = a_w[ab + 8 * ASTR];
        a[2] = a_w[ab + 4];
        a[3] = a_w[ab + 8 * ASTR + 4];
#pragma unroll
        for (int nt = 0; nt < 16; ++nt) {
            int nb = (nt * 8 + g) * ASTR + kk * 8 + tg;
            mma_f16(acc[nt], a, ei_w[nb], ei_w[nb + 4]);
        }
    }
    const int row0 = rblk + r0;
    const int b0 = row0 >> 6, j0r = row0 & 63;
    const int row1 = row0 + 8;
    const int b1 = row1 >> 6, j1r = row1 & 63;
    float* z0p = g_zs + ((size_t)b0 * N_PART + j0r) * KDIM;
    float* z1p = g_zs + ((size_t)b1 * N_PART + j1r) * KDIM;
#pragma unroll
    for (int nt = 0; nt < 16; ++nt) {
        int k0 = nt * 8 + 2 * tg;
        *(float2*)&z0p[k0] = make_float2(acc[nt][0], acc[nt][1]);
        *(float2*)&z1p[k0] = make_float2(acc[nt][2], acc[nt][3]);
    }
}

// ---------------------------------------------------------------------------
// cfconv: R13 exact compute loop; zs staging has an l0 fast path reading
// g_zrow / emb_n (L1-resident) instead of g_zs.
// ---------------------------------------------------------------------------
__global__ void __launch_bounds__(256, 2) cfconv_mma_kernel(
    const float* __restrict__ dists,
    const float* __restrict__ kW1, const float* __restrict__ kb1,
    const float* __restrict__ kW2, const float* __restrict__ kb2,
    const float* __restrict__ emb_n, int l0)
{
    uint32_t* d_sw0 = dyn_smem_w;
    uint32_t* d_sw1 = dyn_smem_w + DBUF_WORDS;
    __half*   h_sh  = (__half*)(dyn_smem_w + OFF_H);
    float*    zs_s  = (float*)(dyn_smem_w + OFF_ZS);
    uint32_t* h_sw  = dyn_smem_w + OFF_H;

    const int tid  = threadIdx.x;
    const int wid  = tid >> 5;
    const int lane = tid & 31;
    const int g    = lane >> 2;
    const int tg   = lane & 3;
    const int m0   = wid * 16 + g;
    const int m1   = m0 + 8;

    const int role = lane >> 3;
    const int rrow = lane & 7;
    const uint32_t ldsm_off = rrow * (DPADW * 4) + (role >> 1) * 32 + (role & 1) * 16;
    const uint32_t ldsm_d0 = smem_u32(d_sw0) + ldsm_off;
    const uint32_t ldsm_d1 = smem_u32(d_sw1) + ldsm_off;
    const uint32_t ldsm_h  = smem_u32(h_sw) + rrow * (HPADW * 4)
                           + (role >> 1) * 32 + (role & 1) * 16;

    uint32_t a1r[2][4];
#pragma unroll
    for (int kk = 0; kk < 2; ++kk) {
        int f = kk * 16 + 2 * tg;
        a1r[kk][0] = pack_h2(kW1[f * KDIM + m0],       kW1[(f + 1) * KDIM + m0]);
        a1r[kk][1] = pack_h2(kW1[f * KDIM + m1],       kW1[(f + 1) * KDIM + m1]);
        a1r[kk][2] = pack_h2(kW1[(f + 8) * KDIM + m0], kW1[(f + 9) * KDIM + m0]);
        a1r[kk][3] = pack_h2(kW1[(f + 8) * KDIM + m1], kW1[(f + 9) * KDIM + m1]);
    }
    uint32_t a2r[8][4];
#pragma unroll
    for (int kk = 0; kk < 8; ++kk) {
        int mm = kk * 16 + 2 * tg;
        a2r[kk][0] = pack_h2(kW2[mm * KDIM + m0],       kW2[(mm + 1) * KDIM + m0]);
        a2r[kk][1] = pack_h2(kW2[mm * KDIM + m1],       kW2[(mm + 1) * KDIM + m1]);
        a2r[kk][2] = pack_h2(kW2[(mm + 8) * KDIM + m0], kW2[(mm + 9) * KDIM + m0]);
        a2r[kk][3] = pack_h2(kW2[(mm + 8) * KDIM + m1], kW2[(mm + 9) * KDIM + m1]);
    }
    const __half2 kb1a2 = __half2half2(__float2half_rn(kb1[m0]));
    const __half2 kb1b2 = __half2half2(__float2half_rn(kb1[m1]));
    const float kb2a = kb2[m0], kb2b = kb2[m1];

    const __half2 D1 = __float2half2_rn( 0.5f);
    const __half2 D2 = __float2half2_rn(-8.3333333e-2f);
    const __half2 D3 = __float2half2_rn( 2.2222222e-2f);
    const __half2 D4 = __float2half2_rn(-6.7460317e-3f);
    const __half2 D5 = __float2half2_rn( 2.1869489e-3f);
    const __half2 HHALF = __float2half2_rn(0.5f);

    const int bi0 = blockIdx.x * TILES_PER_CTA;
    const int b   = bi0 >> 6;

    // prologue: fill d buffer 0 + stage zs (l0: from zrow/emb_n, else g_zs)
    {
        const float* dptr = dists + (size_t)bi0 * (N_PART * BASIS);
        for (int idx = tid; idx < N_PART * (BASIS / 2); idx += 256) {
            int j = idx >> 4, q = idx & 15;
            float2 v = *(const float2*)(dptr + j * BASIS + q * 2);
            d_sw0[j * DPADW + q] = pack_h2(v.x, v.y);
        }
        if (l0) {
            for (int idx = tid; idx < (N_PART * KDIM) / 4; idx += 256) {
                int j = idx >> 5, q = idx & 31;
                const float* src = (j < N_ELEC)
                    ? g_zrow + (j >= N_ELEC / 2 ? KDIM : 0)
                    : emb_n + (j - N_ELEC) * KDIM;
                float4 v = *(const float4*)(src + q * 4);
                *(float4*)&zs_s[j * ZPAD + q * 4] = v;
            }
        } else {
            const float* zsb = g_zs + (size_t)b * (N_PART * KDIM);
            for (int idx = tid; idx < (N_PART * KDIM) / 4; idx += 256) {
                int j = idx >> 5, q = idx & 31;
                float4 v = *(const float4*)(zsb + j * KDIM + q * 4);
                *(float4*)&zs_s[j * ZPAD + q * 4] = v;
            }
        }
    }
    __syncthreads();

#pragma unroll 1
    for (int t = 0; t < TILES_PER_CTA; ++t) {
        const int bi = bi0 + t;
        const int i  = bi & 63;
        const uint32_t ldsm_d = (t & 1) ? ldsm_d1 : ldsm_d0;

        float acc[10][4];
#pragma unroll
        for (int nt = 0; nt < 10; ++nt) {
            acc[nt][0] = 0.0f; acc[nt][1] = 0.0f;
            acc[nt][2] = 0.0f; acc[nt][3] = 0.0f;
        }
#pragma unroll
        for (int nt = 0; nt < 10; ++nt) {
            uint32_t r0, r1, r2, r3;
            LDSM4(r0, r1, r2, r3, ldsm_d + nt * (8 * DPADW * 4));
            mma_f16(acc[nt], a1r[0], r0, r1);
            mma_f16(acc[nt], a1r[1], r2, r3);
        }

        if (t + 1 < TILES_PER_CTA) {
            uint32_t* dnext = ((t + 1) & 1) ? d_sw1 : d_sw0;
            const float* dptr = dists + (size_t)(bi + 1) * (N_PART * BASIS);
            for (int idx = tid; idx < N_PART * (BASIS / 2); idx += 256) {
                int j = idx >> 4, q = idx & 15;
                float2 v = *(const float2*)(dptr + j * BASIS + q * 2);
                dnext[j * DPADW + q] = pack_h2(v.x, v.y);
            }
        }

#pragma unroll
        for (int nt = 0; nt < 10; ++nt) {
            const int j0 = nt * 8 + 2 * tg;
            const int j1 = j0 + 1;
            __half2 x01 = __hadd2(__floats2half2_rn(acc[nt][0], acc[nt][1]), kb1a2);
            __half2 x23 = __hadd2(__floats2half2_rn(acc[nt][2], acc[nt][3]), kb1b2);
            __half2 y01 = __hmul2(x01, HHALF);
            __half2 y23 = __hmul2(x23, HHALF);
            __half2 v01 = __hmul2(y01, y01);
            __half2 v23 = __hmul2(y23, y23);
            __half2 p01 = __hfma2(v01, D5, D4);
            __half2 p23 = __hfma2(v23, D5, D4);
            p01 = __hfma2(v01, p01, D3);  p23 = __hfma2(v23, p23, D3);
            p01 = __hfma2(v01, p01, D2);  p23 = __hfma2(v23, p23, D2);
            p01 = __hfma2(v01, p01, D1);  p23 = __hfma2(v23, p23, D1);
            __half2 h01 = __hfma2(v01, p01, y01);
            __half2 h23 = __hfma2(v23, p23, y23);
            h_sh[j0 * (2 * HPADW) + m0] = __low2half(h01);
            h_sh[j1 * (2 * HPADW) + m0] = __high2half(h01);
            h_sh[j0 * (2 * HPADW) + m1] = __low2half(h23);
            h_sh[j1 * (2 * HPADW) + m1] = __high2half(h23);
        }
        __syncthreads();

#pragma unroll
        for (int nt = 0; nt < 10; ++nt) {
            acc[nt][0] = 0.0f; acc[nt][1] = 0.0f;
            acc[nt][2] = 0.0f; acc[nt][3] = 0.0f;
        }
#pragma unroll
        for (int kp = 0; kp < 8; kp += 2) {
#pragma unroll
            for (int nt = 0; nt < 10; ++nt) {
                uint32_t r0, r1, r2, r3;
                LDSM4(r0, r1, r2, r3, ldsm_h + nt * (8 * HPADW * 4) + kp * 32);
                mma_f16(acc[nt], a2r[kp],     r0, r1);
                mma_f16(acc[nt], a2r[kp + 1], r2, r3);
            }
        }

        float o0 = 0.0f, o1 = 0.0f;
#pragma unroll
        for (int nt = 0; nt < 10; ++nt) {
            const int j0 = nt * 8 + 2 * tg;
            const int j1 = j0 + 1;
            const float w00 = acc[nt][0] + kb2a;
            const float w01 = acc[nt][1] + kb2a;
            const float w10 = acc[nt][2] + kb2b;
            const float w11 = acc[nt][3] + kb2b;
            if (j0 != i) {
                o0 = fmaf(w00, zs_s[j0 * ZPAD + m0], o0);
                o1 = fmaf(w10, zs_s[j0 * ZPAD + m1], o1);
            }
            if (j1 != i) {
                o0 = fmaf(w01, zs_s[j1 * ZPAD + m0], o0);
                o1 = fmaf(w11, zs_s[j1 * ZPAD + m1], o1);
            }
        }
        o0 += __shfl_xor_sync(0xFFFFFFFFu, o0, 1);
        o0 += __shfl_xor_sync(0xFFFFFFFFu, o0, 2);
        o1 += __shfl_xor_sync(0xFFFFFFFFu, o1, 1);
        o1 += __shfl_xor_sync(0xFFFFFFFFu, o1, 2);
        if (tg == 0) {
            g_zsout[(size_t)bi * KDIM + m0] = o0;
            g_zsout[(size_t)bi * KDIM + m1] = o1;
        }
        __syncthreads();
    }
}

// ---------------------------------------------------------------------------
extern "C" void kernel_launch(void* const* d_in, const int* in_sizes, int n_in,
                              void* d_out, int out_size) {
    const float* dists = (const float*)d_in[0];
    const float* emb_e = (const float*)d_in[1];
    const float* emb_n = (const float*)d_in[2];
    const float* kW1   = (const float*)d_in[3];
    const float* kb1   = (const float*)d_in[4];
    const float* kW2   = (const float*)d_in[5];
    const float* kb2   = (const float*)d_in[6];
    const float* eiW   = (const float*)d_in[7];
    const float* eoW1  = (const float*)d_in[8];
    const float* eob1  = (const float*)d_in[9];
    const float* eoW2  = (const float*)d_in[10];
    const float* eob2  = (const float*)d_in[11];
    float* xs = (float*)d_out;

    const int cf_smem = SMEM_WORDS * 4;                    // 76800 B
    const int oz_smem = (4 * 128 * ASTR + 256) * 4;        // 140288 B
    cudaFuncSetAttribute(cfconv_mma_kernel,
                         cudaFuncAttributeMaxDynamicSharedMemorySize, cf_smem);
    cudaFuncSetAttribute(outzs_mma_kernel,
                         cudaFuncAttributeMaxDynamicSharedMemorySize, oz_smem);

    z0_kernel<<<1, 128>>>(emb_e, eiW);
    fill0_kernel<<<(BSZ * N_ELEC * DDIM + 255) / 256, 256>>>(emb_e, emb_n, xs);

    for (int l = 0; l < LAYERS; ++l) {
        cfconv_mma_kernel<<<CFC_GRID, 256, cf_smem>>>(dists,
                                    kW1 + (size_t)l * BASIS * KDIM,
                                    kb1 + (size_t)l * KDIM,
                                    kW2 + (size_t)l * KDIM * KDIM,
                                    kb2 + (size_t)l * KDIM,
                                    emb_n, l == 0 ? 1 : 0);
        const float* eiW_next = (l + 1 < LAYERS)
                              ? eiW + (size_t)(l + 1) * DDIM * KDIM : nullptr;
        outzs_mma_kernel<<<NBI / 128, 256, oz_smem>>>(
                                     eoW1 + (size_t)l * KDIM * DDIM,
                                     eob1 + (size_t)l * DDIM,
                                     eoW2 + (size_t)l * DDIM * DDIM,
                                     eob2 + (size_t)l * DDIM,
                                     eiW_next,
                                     xs);
    }
}